// round 11
// baseline (speedup 1.0000x reference)
#include <cuda_runtime.h>
#include <limits.h>

// RankingLoss over all pairs, N=8192.
// loss = sum_{i,j: dur_i<dur_j, ev_i==1} max(1-(p_i-p_j),0) / count (0 if count==0).
//
// prep_kernel (ONE block, 1024 threads): deterministic stable counting sort by 64
//   duration bins, entirely in smem (no global syncs). Emits bin-sorted j-arrays
//   g_dur/g_pred, pre-compacted event records g_ev = {dur, 1-p, binStart, binEnd},
//   and g_E. Within a bin order is original-index order (stable, deterministic).
// pair_kernel: grid (32 j-chunks x 32 event-chunks). Thread owns one event:
//   exact compare only inside its own bin [lo,hi) (ties handled), unconditional
//   3-op/pair loop over the suffix [hi,N); count is arithmetic. No ballots, no
//   compaction, no per-block classification machinery. Last-arriving block
//   reduces 1024 partials in fixed order. Fully deterministic.

#define NN   8192
#define BINS 64
#define PT   1024
#define PPT  (NN / PT)           // 8 elements per prep thread
#define PWN  (PT / 32)           // 32 warps
#define TPB  256
#define JC   256
#define GJ   (NN / JC)           // 32
#define GI   32                  // event chunks (covers E up to 8192)
#define NBLK (GJ * GI)           // 1024

__device__ float        g_dur[NN];
__device__ float        g_pred[NN];
__device__ float4       g_ev[NN];            // {dur, 1-p, asfloat(lo), asfloat(hi)}
__device__ int          g_E;
__device__ float        g_s[NBLK];
__device__ unsigned int g_c[NBLK];
__device__ unsigned int g_tick = 0u;

__device__ __forceinline__ int dbin(float d) {
    int b = (int)(d * (float)BINS);
    return b < 0 ? 0 : (b > BINS - 1 ? BINS - 1 : b);
}

// ---------------- prep: single-block stable counting sort ---------------------
__global__ void __launch_bounds__(PT)
prep_kernel(const float* __restrict__ preds, const float* __restrict__ targets)
{
    __shared__ int wcA[PWN][BINS], wcE[PWN][BINS];
    __shared__ int histA[BINS], histE[BINS];
    __shared__ int btA[BINS + 1], btE[BINS + 1];
    __shared__ int cumA[BINS], cumE[BINS];

    const int tid = threadIdx.x, wid = tid >> 5, lane = tid & 31;
    const unsigned lt = (1u << lane) - 1u;

    float2 tg[PPT]; float pr[PPT]; int bn[PPT];
    #pragma unroll
    for (int r = 0; r < PPT; ++r) {
        const int e = r * PT + tid;
        tg[r] = ((const float2*)targets)[e];
        pr[r] = preds[e];
        bn[r] = dbin(tg[r].x);
    }

    if (tid < BINS) { histA[tid] = 0; histE[tid] = 0; }
    __syncthreads();

    // phase A: bin totals (warp-aggregated atomics; integer sums -> deterministic)
    #pragma unroll
    for (int r = 0; r < PPT; ++r) {
        const int b = bn[r];
        const bool ev = (tg[r].y == 1.0f);
        const unsigned mm = __match_any_sync(0xffffffffu, b);
        if (__popc(mm & lt) == 0) atomicAdd(&histA[b], __popc(mm));
        const unsigned em  = __ballot_sync(0xffffffffu, ev);
        const unsigned mmE = mm & em;
        if (ev && lane == __ffs(mmE) - 1) atomicAdd(&histE[b], __popc(mmE));
    }
    __syncthreads();

    if (tid == 0) {
        int a = 0, b = 0;
        #pragma unroll
        for (int k = 0; k < BINS; ++k) {
            btA[k] = a; a += histA[k];
            btE[k] = b; b += histE[k];
        }
        btA[BINS] = a;
        btE[BINS] = b;
        g_E = b;
    }
    if (tid < BINS) { cumA[tid] = 0; cumE[tid] = 0; }
    __syncthreads();

    // phase B: stable scatter, round-major / warp-major / lane-major order
    for (int r = 0; r < PPT; ++r) {
        for (int k = tid; k < PWN * BINS; k += PT) {
            ((int*)wcA)[k] = 0;
            ((int*)wcE)[k] = 0;
        }
        __syncthreads();

        const int  b  = bn[r];
        const bool ev = (tg[r].y == 1.0f);
        const unsigned mm  = __match_any_sync(0xffffffffu, b);
        const int      lr  = __popc(mm & lt);
        const unsigned em  = __ballot_sync(0xffffffffu, ev);
        const unsigned mmE = mm & em;
        const int      lrE = __popc(mmE & lt);
        if (lr == 0) wcA[wid][b] = __popc(mm);
        if (ev && lane == __ffs(mmE) - 1) wcE[wid][b] = __popc(mmE);
        __syncthreads();

        int baseA = 0;
        for (int w = 0; w < wid; ++w) baseA += wcA[w][b];
        const int posA = btA[b] + cumA[b] + baseA + lr;
        g_dur[posA]  = tg[r].x;
        g_pred[posA] = pr[r];
        if (ev) {
            int baseE = 0;
            for (int w = 0; w < wid; ++w) baseE += wcE[w][b];
            const int posE = btE[b] + cumE[b] + baseE + lrE;
            g_ev[posE] = make_float4(tg[r].x, 1.0f - pr[r],
                                     __int_as_float(btA[b]),
                                     __int_as_float(btA[b + 1]));
        }
        __syncthreads();

        if (tid < BINS) {
            int sA = 0, sE = 0;
            #pragma unroll
            for (int w = 0; w < PWN; ++w) { sA += wcA[w][tid]; sE += wcE[w][tid]; }
            cumA[tid] += sA;
            cumE[tid] += sE;
        }
        __syncthreads();
    }
}

// ---------------- pair kernel -------------------------------------------------
__global__ void __launch_bounds__(TPB)
pair_kernel(float* __restrict__ out)
{
    __shared__ float sdj[JC], spj[JC];
    __shared__ float        rs[TPB];
    __shared__ unsigned int rc[TPB];
    __shared__ int   s_skip;
    __shared__ int   last_flag;

    const int tid = threadIdx.x;
    const int j0  = blockIdx.x * JC;
    const int i0  = blockIdx.y * TPB;
    const int E   = g_E;

    if (tid == 0) {
        int skip = 1;
        if (i0 < E) {
            const int lof = __float_as_int(g_ev[i0].z);   // min region start in chunk
            skip = (j0 + JC <= lof);
        }
        s_skip = skip;
    }
    __syncthreads();

    float s0 = 0.0f, s1 = 0.0f, s2 = 0.0f, s3 = 0.0f;
    unsigned int cnt = 0u;

    if (!s_skip) {
        // tile load
        for (int t = tid; t < JC; t += TPB) {
            sdj[t] = g_dur[j0 + t];
            spj[t] = g_pred[j0 + t];
        }
        __syncthreads();

        const int idx = i0 + tid;
        if (idx < E) {
            const float4 ev = g_ev[idx];
            const float dur = ev.x;
            const float c   = ev.y;
            const int   lo  = __float_as_int(ev.z);
            const int   hi  = __float_as_int(ev.w);

            // exact-compare region: own bin ∩ tile
            const int a = max(lo - j0, 0);
            const int b = min(hi - j0, JC);
            for (int j = a; j < b; ++j) {
                if (dur < sdj[j]) { s0 += fmaxf(c + spj[j], 0.0f); cnt++; }
            }

            // unconditional suffix region: [hi, N) ∩ tile
            int f = hi - j0;
            if (f < 0) f = 0;
            if (f < JC) {
                cnt += (unsigned int)(JC - f);
                int j = f;
                for (; (j & 3) && j < JC; ++j) s0 += fmaxf(c + spj[j], 0.0f);
                const float4* sp4 = (const float4*)spj;
                for (int t = j >> 2; t < JC / 4; ++t) {
                    const float4 P = sp4[t];
                    s0 += fmaxf(c + P.x, 0.0f);
                    s1 += fmaxf(c + P.y, 0.0f);
                    s2 += fmaxf(c + P.z, 0.0f);
                    s3 += fmaxf(c + P.w, 0.0f);
                }
            }
        }
    }

    // deterministic block reduction
    rs[tid] = (s0 + s1) + (s2 + s3);
    rc[tid] = cnt;
    __syncthreads();
    #pragma unroll
    for (int o = TPB / 2; o > 0; o >>= 1) {
        if (tid < o) { rs[tid] += rs[tid + o]; rc[tid] += rc[tid + o]; }
        __syncthreads();
    }

    if (tid == 0) {
        const int slot = blockIdx.y * GJ + blockIdx.x;
        g_s[slot] = rs[0];
        g_c[slot] = rc[0];
        __threadfence();
        last_flag = (atomicAdd(&g_tick, 1u) == NBLK - 1u) ? 1 : 0;
    }
    __syncthreads();

    if (last_flag) {
        __threadfence();
        rs[tid] = (g_s[tid] + g_s[tid + TPB]) + (g_s[tid + 2 * TPB] + g_s[tid + 3 * TPB]);
        rc[tid] = (g_c[tid] + g_c[tid + TPB]) + (g_c[tid + 2 * TPB] + g_c[tid + 3 * TPB]);
        __syncthreads();
        #pragma unroll
        for (int o = TPB / 2; o > 0; o >>= 1) {
            if (tid < o) { rs[tid] += rs[tid + o]; rc[tid] += rc[tid + o]; }
            __syncthreads();
        }
        if (tid == 0) {
            out[0] = (rc[0] > 0u) ? (rs[0] / (float)rc[0]) : 0.0f;
            g_tick = 0u;   // reset for next graph replay
        }
    }
}

extern "C" void kernel_launch(void* const* d_in, const int* in_sizes, int n_in,
                              void* d_out, int out_size)
{
    const float* preds   = (const float*)d_in[0];   // [8192]
    const float* targets = (const float*)d_in[1];   // [8192,2] {dur, ev}
    float* out = (float*)d_out;

    prep_kernel<<<1, PT>>>(preds, targets);
    dim3 grid(GJ, GI);
    pair_kernel<<<grid, TPB>>>(out);
}

// round 13
// speedup vs baseline: 1.3934x; 1.3934x over previous
#include <cuda_runtime.h>

// RankingLoss over all pairs, N=8192.
// loss = sum_{i,j: dur_i<dur_j, ev_i==1} max(1-(p_i-p_j),0) / count (0 if count==0).
//
// prep (1 block, 1024 threads, single count->scan->scatter pass, no rounds):
//   counting sort by 64 duration bins into g_dur/g_pred; events additionally
//   compacted into g_evt {dur, 1-p, lo, hi}. Order within a bin is the fixed
//   (round,warp,lane) order -> deterministic. Bins strictly separate durations,
//   so compare region = own bin, suffix [hi,N) is unconditionally valid.
// pair (grid 32 j-segs x 16 event-chunks, 512 threads): thread owns one event;
//   exact compare in own-bin∩tile, 3-op/pair unconditional suffix, arithmetic
//   count. Skip blocks exit before tile load. Last-arriving block reduces all
//   512 partials in fixed order. Fully deterministic.

#define NN   8192
#define BINS 64
#define PT   1024
#define PPT  (NN / PT)            // 8
#define PWN  (PT / 32)            // 32
#define RW   (PPT * PWN)          // 256 (round,warp) slots
#define TPB  512
#define JSEG 256
#define GJ   (NN / JSEG)          // 32
#define GE   (NN / TPB)           // 16 event chunks (covers E up to 8192)
#define NBLK (GJ * GE)            // 512

__device__ float        g_dur[NN];
__device__ float        g_pred[NN];
__device__ float4       g_evt[NN];     // {dur, 1-p, asfloat(lo), asfloat(hi)}
__device__ int          g_E;
__device__ float        g_s[NBLK];
__device__ unsigned int g_c[NBLK];
__device__ unsigned int g_tick = 0u;

__device__ __forceinline__ int dbin(float d) {
    int b = (int)(d * (float)BINS);
    return b < 0 ? 0 : (b > BINS - 1 ? BINS - 1 : b);
}

// ---------------- prep: one-pass deterministic counting sort ------------------
__global__ void __launch_bounds__(PT)
prep_kernel(const float* __restrict__ preds, const float* __restrict__ targets)
{
    extern __shared__ unsigned short s_cnt[];      // [2][RW][BINS] shorts = 64KB
    unsigned short* cA = s_cnt;                    // all elements
    unsigned short* cE = s_cnt + RW * BINS;        // events only
    __shared__ int btA[BINS + 1], btE[BINS + 1];
    __shared__ int totA[BINS], totE[BINS];

    const int tid = threadIdx.x, wid = tid >> 5, lane = tid & 31;
    const unsigned lt = (1u << lane) - 1u;

    // zero counts (64KB = 16384 uints)
    for (int k = tid; k < RW * BINS; k += PT) ((unsigned int*)s_cnt)[k] = 0u;

    float du[PPT], evf[PPT], pr[PPT];
    #pragma unroll
    for (int r = 0; r < PPT; ++r) {
        const int e = r * PT + tid;
        const float2 tg = ((const float2*)targets)[e];
        du[r] = tg.x; evf[r] = tg.y; pr[r] = preds[e];
    }
    __syncthreads();

    // count pass: leaders write per-(round,warp,bin) group sizes (distinct slots)
    #pragma unroll
    for (int r = 0; r < PPT; ++r) {
        const int b = dbin(du[r]);
        const bool ev = (evf[r] == 1.0f);
        const unsigned mm = __match_any_sync(0xffffffffu, b);
        if (__popc(mm & lt) == 0)
            cA[(r * PWN + wid) * BINS + b] = (unsigned short)__popc(mm);
        const unsigned em  = __ballot_sync(0xffffffffu, ev);
        const unsigned mmE = mm & em;
        if (ev && lane == (__ffs(mmE) - 1))
            cE[(r * PWN + wid) * BINS + b] = (unsigned short)__popc(mmE);
    }
    __syncthreads();

    // per-bin exclusive scan over the 256 (round,warp) slots; 128 threads work
    if (tid < 2 * BINS) {
        unsigned short* c = (tid < BINS) ? cA : cE;
        const int b = (tid < BINS) ? tid : (tid - BINS);
        int acc = 0;
        for (int f = 0; f < RW; ++f) {
            const int v = c[f * BINS + b];
            c[f * BINS + b] = (unsigned short)acc;
            acc += v;
        }
        if (tid < BINS) totA[b] = acc; else totE[b] = acc;
    }
    __syncthreads();
    if (tid == 0) {
        int a = 0;
        #pragma unroll
        for (int b = 0; b < BINS; ++b) { btA[b] = a; a += totA[b]; }
        btA[BINS] = a;
    }
    if (tid == 1) {
        int a = 0;
        #pragma unroll
        for (int b = 0; b < BINS; ++b) { btE[b] = a; a += totE[b]; }
        btE[BINS] = a;
        g_E = a;
    }
    __syncthreads();

    // scatter pass (recompute match -> identical deterministic ranks)
    #pragma unroll
    for (int r = 0; r < PPT; ++r) {
        const int b = dbin(du[r]);
        const bool ev = (evf[r] == 1.0f);
        const unsigned mm = __match_any_sync(0xffffffffu, b);
        const int lr = __popc(mm & lt);
        const int posA = btA[b] + (int)cA[(r * PWN + wid) * BINS + b] + lr;
        g_dur[posA]  = du[r];
        g_pred[posA] = pr[r];
        const unsigned em  = __ballot_sync(0xffffffffu, ev);
        const unsigned mmE = mm & em;
        if (ev) {
            const int lrE  = __popc(mmE & lt);
            const int posE = btE[b] + (int)cE[(r * PWN + wid) * BINS + b] + lrE;
            g_evt[posE] = make_float4(du[r], 1.0f - pr[r],
                                      __int_as_float(btA[b]),
                                      __int_as_float(btA[b + 1]));
        }
    }
}

// ---------------- pair kernel -------------------------------------------------
__global__ void __launch_bounds__(TPB)
pair_kernel(float* __restrict__ out)
{
    __shared__ float sdj[JSEG], spj[JSEG];
    __shared__ float        rs[TPB];
    __shared__ unsigned int rc[TPB];
    __shared__ int s_skip, last_flag;

    const int tid = threadIdx.x;
    const int j0  = blockIdx.x * JSEG;
    const int i0  = blockIdx.y * TPB;
    const int E   = g_E;

    if (tid == 0) {
        int skip = 1;
        if (i0 < E) {
            const int lo0 = __float_as_int(g_evt[i0].z);  // lo non-decreasing in i
            skip = (j0 + JSEG <= lo0);
        }
        s_skip = skip;
    }
    __syncthreads();

    float s0 = 0.0f, s1 = 0.0f, s2 = 0.0f, s3 = 0.0f;
    unsigned int cnt = 0u;

    if (!s_skip) {
        for (int t = tid; t < JSEG; t += TPB) {
            sdj[t] = g_dur[j0 + t];
            spj[t] = g_pred[j0 + t];
        }
        __syncthreads();

        const int idx = i0 + tid;
        if (idx < E) {
            const float4 ev = g_evt[idx];
            const float dur = ev.x;
            const float c   = ev.y;
            const int   lo  = __float_as_int(ev.z);
            const int   hi  = __float_as_int(ev.w);

            // exact-compare region: own bin ∩ tile (handles duration ties)
            const int a = max(lo - j0, 0);
            const int b = min(hi - j0, JSEG);
            for (int j = a; j < b; ++j) {
                if (dur < sdj[j]) { s0 += fmaxf(c + spj[j], 0.0f); cnt++; }
            }

            // unconditional suffix region: [hi, N) ∩ tile  (3 ops/pair)
            int f = hi - j0;
            if (f < 0) f = 0;
            if (f < JSEG) {
                cnt += (unsigned int)(JSEG - f);
                int j = f;
                for (; (j & 3) && j < JSEG; ++j) s0 += fmaxf(c + spj[j], 0.0f);
                const float4* sp4 = (const float4*)spj;
                #pragma unroll 8
                for (int t = j >> 2; t < JSEG / 4; ++t) {
                    const float4 P = sp4[t];
                    s0 += fmaxf(c + P.x, 0.0f);
                    s1 += fmaxf(c + P.y, 0.0f);
                    s2 += fmaxf(c + P.z, 0.0f);
                    s3 += fmaxf(c + P.w, 0.0f);
                }
            }
        }
    }

    // deterministic block reduction
    rs[tid] = (s0 + s1) + (s2 + s3);
    rc[tid] = cnt;
    __syncthreads();
    #pragma unroll
    for (int o = TPB / 2; o > 0; o >>= 1) {
        if (tid < o) { rs[tid] += rs[tid + o]; rc[tid] += rc[tid + o]; }
        __syncthreads();
    }

    if (tid == 0) {
        const int slot = blockIdx.y * GJ + blockIdx.x;
        g_s[slot] = rs[0];
        g_c[slot] = rc[0];
        __threadfence();
        last_flag = (atomicAdd(&g_tick, 1u) == NBLK - 1u) ? 1 : 0;
    }
    __syncthreads();

    if (last_flag) {
        __threadfence();
        rs[tid] = g_s[tid];
        rc[tid] = g_c[tid];
        __syncthreads();
        #pragma unroll
        for (int o = TPB / 2; o > 0; o >>= 1) {
            if (tid < o) { rs[tid] += rs[tid + o]; rc[tid] += rc[tid + o]; }
            __syncthreads();
        }
        if (tid == 0) {
            out[0] = (rc[0] > 0u) ? (rs[0] / (float)rc[0]) : 0.0f;
            g_tick = 0u;                 // reset for next graph replay
        }
    }
}

extern "C" void kernel_launch(void* const* d_in, const int* in_sizes, int n_in,
                              void* d_out, int out_size)
{
    const float* preds   = (const float*)d_in[0];   // [8192]
    const float* targets = (const float*)d_in[1];   // [8192,2] {dur, ev}
    float* out = (float*)d_out;

    const int prep_smem = 2 * RW * BINS * (int)sizeof(unsigned short);  // 64KB
    cudaFuncSetAttribute(prep_kernel, cudaFuncAttributeMaxDynamicSharedMemorySize,
                         prep_smem);

    prep_kernel<<<1, PT, prep_smem>>>(preds, targets);
    dim3 grid(GJ, GE);
    pair_kernel<<<grid, TPB>>>(out);
}